// round 1
// baseline (speedup 1.0000x reference)
#include <cuda_runtime.h>

#define Bb 2
#define Nn 512
#define Ff 128
#define TI 8
#define TJ 16
#define TE 128
#define BUFS 132
#define AJS 129
#define BMS 129

typedef unsigned long long u64;

// scratch (device globals; no allocation allowed)
__device__ float g_A[Bb*Nn*Ff];      // h_masked @ edge_w1[0:F]          (source/j term)
__device__ float g_Bm[Bb*Nn*Ff];     // h_masked @ edge_w1[F:2F] + b1    (target/i term)
__device__ float g_hm[Bb*Nn*Ff];     // h * mask
__device__ float g_agg[Bb*Nn*Ff];    // sum_j m
__device__ float g_trans[Bb*Nn*3];   // sum_j coord_diff*embed*mask2d

__device__ __forceinline__ float silu_f(float x) { return x / (1.f + __expf(-x)); }

__device__ __forceinline__ u64 pack2(float x) {
    u64 r; asm("mov.b64 %0, {%1, %1};" : "=l"(r) : "f"(x)); return r;
}
__device__ __forceinline__ void ffma2(u64 &d, u64 a, u64 b) {
    asm("fma.rn.f32x2 %0, %1, %2, %0;" : "+l"(d) : "l"(a), "l"(b));
}
__device__ __forceinline__ float2 unpack2(u64 v) {
    float2 r; asm("mov.b64 {%0, %1}, %2;" : "=f"(r.x), "=f"(r.y) : "l"(v)); return r;
}

// ---------------------------------------------------------------------------
// k_prep: hm = h*mask ; A = hm @ W1a ; Bm = hm @ W1b + b1
// grid = B*N blocks, 128 threads
// ---------------------------------------------------------------------------
__global__ __launch_bounds__(128) void k_prep(
    const float* __restrict__ h, const float* __restrict__ mask,
    const float* __restrict__ ew1, const float* __restrict__ eb1)
{
    __shared__ float hr[Ff];
    const int r = blockIdx.x;
    const int t = threadIdx.x;
    const float mk = mask[r];
    float hv = h[r*Ff + t] * mk;
    hr[t] = hv;
    g_hm[r*Ff + t] = hv;
    __syncthreads();
    float a = 0.f;
    float bm = eb1[t];
    #pragma unroll 8
    for (int k = 0; k < Ff; k++) {
        float hk = hr[k];
        a  += hk * ew1[k*Ff + t];
        bm += hk * ew1[(Ff + k)*Ff + t];
    }
    g_A[r*Ff + t]  = a;
    g_Bm[r*Ff + t] = bm;
}

// ---------------------------------------------------------------------------
// k_edge: fused edge model + coord model + aggregations
// grid = B*(N/TI) = 128 blocks, 256 threads, ~210KB dynamic smem
// ---------------------------------------------------------------------------
__global__ __launch_bounds__(256, 1) void k_edge(
    const float* __restrict__ coord, const float* __restrict__ mask,
    const float* __restrict__ ew1,   const float* __restrict__ eb2,
    const float* __restrict__ ew2,   const float* __restrict__ cw1,
    const float* __restrict__ cb1,   const float* __restrict__ cw2)
{
    extern __shared__ float sm[];
    float* W2s  = sm;            // 128*128
    float* C1s  = sm + 16384;    // 128*128
    float* buf  = sm + 32768;    // 128*BUFS (m1T, then m row-major, then agg staging)
    float* Ajs  = sm + 49664;    // TJ*AJS
    float* Bms  = sm + 51728;    // TI*BMS
    float* w1c  = sm + 52760;    // 128
    float* b2s  = sm + 52888;    // 128
    float* cb1s = sm + 53016;    // 128
    float* cw2s = sm + 53144;    // 128
    float* rad  = sm + 53272;    // 128
    float* m2d  = sm + 53400;    // 128
    float* emb  = sm + 53528;    // 128
    float* ci   = sm + 53656;    // TI*3
    float* mi   = sm + 53680;    // TI
    float* cj   = sm + 53688;    // TJ*3
    float* mj   = sm + 53736;    // TJ
    float* trs  = sm + 53752;    // TI*3

    const int tid = threadIdx.x;
    const int b  = blockIdx.x / (Nn/TI);
    const int i0 = (blockIdx.x % (Nn/TI)) * TI;
    const int ty = tid >> 4, tx = tid & 15;
    const int e0 = ty*8, f0 = tx*8;

    // setup: weights + i-tile data
    for (int idx = tid; idx < Ff*Ff; idx += 256) { W2s[idx] = ew2[idx]; C1s[idx] = cw1[idx]; }
    if (tid < Ff) {
        w1c[tid]  = ew1[2*Ff*Ff + tid];
        b2s[tid]  = eb2[tid];
        cb1s[tid] = cb1[tid];
        cw2s[tid] = cw2[tid];
    }
    if (tid < TI) {
        float mk = mask[b*Nn + i0 + tid];
        mi[tid] = mk;
        ci[tid*3+0] = coord[(b*Nn+i0+tid)*3+0]*mk;
        ci[tid*3+1] = coord[(b*Nn+i0+tid)*3+1]*mk;
        ci[tid*3+2] = coord[(b*Nn+i0+tid)*3+2]*mk;
    }
    if (tid < TI*3) trs[tid] = 0.f;
    for (int idx = tid; idx < TI*Ff; idx += 256) {
        int ii = idx >> 7, f = idx & 127;
        Bms[ii*BMS + f] = g_Bm[(b*Nn + i0 + ii)*Ff + f];
    }
    float agg[8];
    #pragma unroll
    for (int q = 0; q < 8; q++) agg[q] = 0.f;

    for (int jt = 0; jt < Nn/TJ; jt++) {
        const int j0 = jt*TJ;
        __syncthreads();   // protects Ajs/cj/mj/buf reuse from previous iteration
        for (int idx = tid; idx < TJ*Ff; idx += 256) {
            int jj = idx >> 7, f = idx & 127;
            Ajs[jj*AJS + f] = g_A[(b*Nn + j0 + jj)*Ff + f];
        }
        if (tid < TJ) {
            float mk = mask[b*Nn + j0 + tid];
            mj[tid] = mk;
            cj[tid*3+0] = coord[(b*Nn+j0+tid)*3+0]*mk;
            cj[tid*3+1] = coord[(b*Nn+j0+tid)*3+1]*mk;
            cj[tid*3+2] = coord[(b*Nn+j0+tid)*3+2]*mk;
        }
        __syncthreads();
        // radial + mask2d per edge
        if (tid < TE) {
            int ii = tid >> 4, jj = tid & 15;
            float m2 = mi[ii]*mj[jj];
            float dx = ci[ii*3+0]-cj[jj*3+0];
            float dy = ci[ii*3+1]-cj[jj*3+1];
            float dz = ci[ii*3+2]-cj[jj*3+2];
            rad[tid] = (dx*dx + dy*dy + dz*dz)*m2;
            m2d[tid] = m2;
        }
        __syncthreads();
        // build m1T[f][e] = silu(A[j] + Bm[i] + radial*w1c)
        for (int idx = tid; idx < TE*Ff; idx += 256) {
            int e = idx & 127, f = idx >> 7;
            int ii = e >> 4, jj = e & 15;
            float x = Ajs[jj*AJS + f] + Bms[ii*BMS + f] + rad[e]*w1c[f];
            buf[f*BUFS + e] = silu_f(x);
        }
        __syncthreads();

        // ---- GEMM2: m = silu(m1 @ W2 + b2) * mask2d ----
        u64 C[8][4];
        #pragma unroll
        for (int ee = 0; ee < 8; ee++)
            #pragma unroll
            for (int p = 0; p < 4; p++) C[ee][p] = 0ULL;
        #pragma unroll 4
        for (int k = 0; k < Ff; k++) {
            const float* ar = buf + k*BUFS + e0;
            float4 a0 = *(const float4*)ar;
            float4 a1 = *(const float4*)(ar + 4);
            u64 ap[8] = {pack2(a0.x), pack2(a0.y), pack2(a0.z), pack2(a0.w),
                         pack2(a1.x), pack2(a1.y), pack2(a1.z), pack2(a1.w)};
            const u64* wr = (const u64*)(W2s + k*Ff + f0);
            u64 wp0 = wr[0], wp1 = wr[1], wp2 = wr[2], wp3 = wr[3];
            #pragma unroll
            for (int ee = 0; ee < 8; ee++) {
                ffma2(C[ee][0], ap[ee], wp0);
                ffma2(C[ee][1], ap[ee], wp1);
                ffma2(C[ee][2], ap[ee], wp2);
                ffma2(C[ee][3], ap[ee], wp3);
            }
        }
        float mm[8][8];
        #pragma unroll
        for (int ee = 0; ee < 8; ee++) {
            float m2 = m2d[e0+ee];
            #pragma unroll
            for (int p = 0; p < 4; p++) {
                float2 v = unpack2(C[ee][p]);
                float x0 = silu_f(v.x + b2s[f0+2*p  ])*m2;
                float x1 = silu_f(v.y + b2s[f0+2*p+1])*m2;
                mm[ee][2*p]   = x0;
                mm[ee][2*p+1] = x1;
                agg[2*p]   += x0;
                agg[2*p+1] += x1;
            }
        }
        __syncthreads();   // all GEMM2 reads of buf complete
        #pragma unroll
        for (int ee = 0; ee < 8; ee++) {
            *(float4*)(buf + (e0+ee)*BUFS + f0)     = make_float4(mm[ee][0],mm[ee][1],mm[ee][2],mm[ee][3]);
            *(float4*)(buf + (e0+ee)*BUFS + f0 + 4) = make_float4(mm[ee][4],mm[ee][5],mm[ee][6],mm[ee][7]);
        }
        __syncthreads();

        // ---- GEMM3: p = silu(m @ coord_w1 + cb1);  embed = p @ coord_w2 ----
        #pragma unroll
        for (int ee = 0; ee < 8; ee++)
            #pragma unroll
            for (int p = 0; p < 4; p++) C[ee][p] = 0ULL;
        #pragma unroll 4
        for (int k = 0; k < Ff; k++) {
            u64 ap[8];
            #pragma unroll
            for (int ee = 0; ee < 8; ee++) ap[ee] = pack2(buf[(e0+ee)*BUFS + k]);
            const u64* wr = (const u64*)(C1s + k*Ff + f0);
            u64 wp0 = wr[0], wp1 = wr[1], wp2 = wr[2], wp3 = wr[3];
            #pragma unroll
            for (int ee = 0; ee < 8; ee++) {
                ffma2(C[ee][0], ap[ee], wp0);
                ffma2(C[ee][1], ap[ee], wp1);
                ffma2(C[ee][2], ap[ee], wp2);
                ffma2(C[ee][3], ap[ee], wp3);
            }
        }
        float pe[8];
        #pragma unroll
        for (int ee = 0; ee < 8; ee++) pe[ee] = 0.f;
        #pragma unroll
        for (int ee = 0; ee < 8; ee++) {
            #pragma unroll
            for (int p = 0; p < 4; p++) {
                float2 v = unpack2(C[ee][p]);
                pe[ee] += silu_f(v.x + cb1s[f0+2*p  ])*cw2s[f0+2*p  ];
                pe[ee] += silu_f(v.y + cb1s[f0+2*p+1])*cw2s[f0+2*p+1];
            }
        }
        // reduce across the 16 tx lanes (lanes 0-15 / 16-31 within each warp)
        #pragma unroll
        for (int ee = 0; ee < 8; ee++) {
            pe[ee] += __shfl_xor_sync(0xffffffffu, pe[ee], 8);
            pe[ee] += __shfl_xor_sync(0xffffffffu, pe[ee], 4);
            pe[ee] += __shfl_xor_sync(0xffffffffu, pe[ee], 2);
            pe[ee] += __shfl_xor_sync(0xffffffffu, pe[ee], 1);
        }
        if (tx == 0) {
            #pragma unroll
            for (int ee = 0; ee < 8; ee++) emb[e0+ee] = pe[ee];
        }
        __syncthreads();
        // trans accumulation (deterministic: 24 threads, fixed order)
        if (tid < TI*3) {
            int ii = tid/3, d = tid - ii*3;
            float cid = ci[ii*3+d];
            float s = 0.f;
            #pragma unroll
            for (int jj = 0; jj < TJ; jj++) {
                int e = ii*16 + jj;
                float m2 = m2d[e];
                s += (cid - cj[jj*3+d])*m2*emb[e]*m2;
            }
            trs[tid] += s;
        }
    }
    __syncthreads();

    // agg: combine the two jj-halves (ty parity), then write
    {
        float* ags = buf;  // reuse as [8][128]
        int ii = ty >> 1;
        if ((ty & 1) == 0) {
            #pragma unroll
            for (int q = 0; q < 8; q++) ags[ii*128 + f0 + q] = agg[q];
        }
        __syncthreads();
        if ((ty & 1) == 1) {
            #pragma unroll
            for (int q = 0; q < 8; q++) ags[ii*128 + f0 + q] += agg[q];
        }
        __syncthreads();
        for (int idx = tid; idx < TI*Ff; idx += 256) {
            int ii2 = idx >> 7, f = idx & 127;
            g_agg[(b*Nn + i0 + ii2)*Ff + f] = ags[ii2*128 + f];
        }
        if (tid < TI*3) g_trans[(b*Nn + i0 + tid/3)*3 + (tid % 3)] = trs[tid];
    }
}

// ---------------------------------------------------------------------------
// k_node: node MLP + residual + coord finalize; writes d_out
// grid = B*N blocks, 128 threads
// ---------------------------------------------------------------------------
__global__ __launch_bounds__(128) void k_node(
    const float* __restrict__ coord, const float* __restrict__ mask,
    const float* __restrict__ nw1, const float* __restrict__ nb1,
    const float* __restrict__ nw2, const float* __restrict__ nb2,
    float* __restrict__ out)
{
    __shared__ float nin[2*Ff];
    __shared__ float t1s[Ff];
    __shared__ float red[Ff];
    const int r = blockIdx.x;
    const int t = threadIdx.x;
    const int b = r >> 9;
    const float mk = mask[r];
    const float hm = g_hm[r*Ff + t];
    nin[t]      = hm * mk;
    nin[Ff + t] = g_agg[r*Ff + t] * mk;
    float s = 0.f;
    for (int q = t; q < Nn; q += 128) s += mask[b*Nn + q];
    red[t] = s;
    __syncthreads();
    for (int off = 64; off >= 1; off >>= 1) {
        if (t < off) red[t] += red[t + off];
        __syncthreads();
    }
    float acc = nb1[t];
    #pragma unroll 8
    for (int k = 0; k < 2*Ff; k++) acc += nin[k]*nw1[k*Ff + t];
    t1s[t] = silu_f(acc);
    __syncthreads();
    float acc2 = nb2[t];
    #pragma unroll 8
    for (int k = 0; k < Ff; k++) acc2 += t1s[k]*nw2[k*Ff + t];
    out[r*Ff + t] = (hm + acc2)*mk;
    if (t < 3) {
        float denom = mk*red[0] + 1e-10f;
        float cm = coord[r*3 + t]*mk;
        out[Bb*Nn*Ff + r*3 + t] = (cm + g_trans[r*3 + t]/denom)*mk;
    }
}

// ---------------------------------------------------------------------------
extern "C" void kernel_launch(void* const* d_in, const int* in_sizes, int n_in,
                              void* d_out, int out_size)
{
    const float* h     = (const float*)d_in[0];
    const float* coord = (const float*)d_in[1];
    const float* mask  = (const float*)d_in[2];
    const float* ew1   = (const float*)d_in[3];
    const float* eb1   = (const float*)d_in[4];
    const float* ew2   = (const float*)d_in[5];
    const float* eb2   = (const float*)d_in[6];
    const float* nw1   = (const float*)d_in[7];
    const float* nb1   = (const float*)d_in[8];
    const float* nw2   = (const float*)d_in[9];
    const float* nb2   = (const float*)d_in[10];
    const float* cw1   = (const float*)d_in[11];
    const float* cb1   = (const float*)d_in[12];
    const float* cw2   = (const float*)d_in[13];

    const int smem_bytes = 53776 * 4;
    cudaFuncSetAttribute(k_edge, cudaFuncAttributeMaxDynamicSharedMemorySize, smem_bytes);

    k_prep<<<Bb*Nn, 128>>>(h, mask, ew1, eb1);
    k_edge<<<Bb*(Nn/TI), 256, smem_bytes>>>(coord, mask, ew1, eb2, ew2, cw1, cb1, cw2);
    k_node<<<Bb*Nn, 128>>>(coord, mask, nw1, nb1, nw2, nb2, (float*)d_out);
}